// round 4
// baseline (speedup 1.0000x reference)
#include <cuda_runtime.h>
#include <cuda_bf16.h>
#include <mma.h>

using namespace nvcuda;

#define NN 100000
#define EE 800000
#define HID 128
#define NB_SCAN 98   // ceil(NN/1024)

// ---------------- scratch (static device globals; no allocation) -------------
__device__ int   g_cnt[NN];
__device__ int   g_rowptr[NN + 1];
__device__ int   g_wptr[NN];
__device__ float g_dinv[NN];
__device__ int   g_colsrc[EE];
__device__ float g_h0[NN * 16];
__device__ float g_h0s[NN * 16];     // h0 * dinv (pre-scaled for gather)
__device__ float g_agg[NN * HID];
__device__ float g_hs[NN * HID];     // relu(h) * dinv (pre-scaled for gather)
__device__ float g_emb[NN * HID];
__device__ int   g_bsum[128];
__device__ int   g_bsumx[128];
__device__ __nv_bfloat16 g_whi[5 * 128 * 128];  // Wh[0..3], Wr1 (hi)
__device__ __nv_bfloat16 g_wlo[5 * 128 * 128];  // (lo)

// ---------------- graph preprocessing ----------------------------------------

__global__ void k_init(const float* __restrict__ x, const float* __restrict__ xm) {
    int i = blockIdx.x * blockDim.x + threadIdx.x;
    if (i < NN) {
        g_cnt[i] = 0;
#pragma unroll
        for (int c = 0; c < 8; c++) {
            g_h0[i * 16 + c]     = x[i * 10 + c];
            g_h0[i * 16 + 8 + c] = xm[i * 10 + c];
        }
    }
}

__global__ void k_count(const int* __restrict__ ei) {
    int e = blockIdx.x * blockDim.x + threadIdx.x;
    if (e < EE) atomicAdd(&g_cnt[ei[EE + e]], 1);
}

// split weights into bf16 hi + lo (Wh[0..3] then Wr1)
__global__ void k_wsplit(const float* __restrict__ Wh, const float* __restrict__ Wr1) {
    int i = blockIdx.x * blockDim.x + threadIdx.x;
    if (i >= 5 * 128 * 128) return;
    float v = (i < 4 * 128 * 128) ? Wh[i] : Wr1[i - 4 * 128 * 128];
    __nv_bfloat16 hi = __float2bfloat16(v);
    g_whi[i] = hi;
    g_wlo[i] = __float2bfloat16(v - __bfloat162float(hi));
}

// pass 1: per-block exclusive scan; also compute dinv
__global__ void k_scan1() {
    __shared__ int sdata[1024];
    int t = threadIdx.x;
    int i = blockIdx.x * 1024 + t;
    int v = (i < NN) ? g_cnt[i] : 0;
    if (i < NN) g_dinv[i] = rsqrtf((float)v + 1.0f);
    sdata[t] = v;
    __syncthreads();
#pragma unroll
    for (int off = 1; off < 1024; off <<= 1) {
        int x = (t >= off) ? sdata[t - off] : 0;
        __syncthreads();
        sdata[t] += x;
        __syncthreads();
    }
    if (i < NN) {
        int excl = sdata[t] - v;
        g_rowptr[i] = excl;
        g_wptr[i]   = excl;
    }
    if (t == 1023) g_bsum[blockIdx.x] = sdata[1023];
}

// pass 2: scan the 98 block sums
__global__ void k_scan2() {
    __shared__ int sdata[128];
    int t = threadIdx.x;
    int v = (t < NB_SCAN) ? g_bsum[t] : 0;
    sdata[t] = v;
    __syncthreads();
#pragma unroll
    for (int off = 1; off < 128; off <<= 1) {
        int x = (t >= off) ? sdata[t - off] : 0;
        __syncthreads();
        sdata[t] += x;
        __syncthreads();
    }
    if (t < NB_SCAN) g_bsumx[t] = sdata[t] - v;
}

// pass 3: add block offsets; also build h0s = h0 * dinv
__global__ void k_scan3() {
    int i = blockIdx.x * blockDim.x + threadIdx.x;
    if (i < NN) {
        int off = g_bsumx[i >> 10];
        g_rowptr[i] += off;
        g_wptr[i]   += off;
        float dv = g_dinv[i];
#pragma unroll
        for (int c = 0; c < 16; c++)
            g_h0s[i * 16 + c] = g_h0[i * 16 + c] * dv;
    }
    if (i == 0) g_rowptr[NN] = EE;
}

__global__ void k_fill(const int* __restrict__ ei) {
    int e = blockIdx.x * blockDim.x + threadIdx.x;
    if (e < EE) {
        int s = ei[e];
        int d = ei[EE + e];
        int p = atomicAdd(&g_wptr[d], 1);
        g_colsrc[p] = s;
    }
}

// ---------------- aggregation (gather over CSR, pre-scaled inputs) ------------
// Predicated batch-of-8: 8 independent index loads + 8 independent gathers
// issue before any consume -> MLP=8, no serial tail.

// layer-0: 16 channels, 16 lanes per node
__global__ void k_agg16() {
    int tid = blockIdx.x * blockDim.x + threadIdx.x;
    int v = tid >> 4;
    int c = tid & 15;
    if (v >= NN) return;
    float dv = g_dinv[v];
    float acc = g_h0s[v * 16 + c];
    int beg = g_rowptr[v], end = g_rowptr[v + 1];
    for (int b = beg; b < end; b += 8) {
        int n = end - b;
        float x[8];
        int   u[8];
#pragma unroll
        for (int j = 0; j < 8; j++) u[j] = (j < n) ? g_colsrc[b + j] : 0;
#pragma unroll
        for (int j = 0; j < 8; j++)
            x[j] = (j < n) ? __ldg(g_h0s + u[j] * 16 + c) : 0.f;
        acc += ((x[0] + x[1]) + (x[2] + x[3])) + ((x[4] + x[5]) + (x[6] + x[7]));
    }
    g_agg[v * 16 + c] = acc * dv;
}

// 128-channel: warp per node, float4 per lane, predicated batch-of-8
__global__ void __launch_bounds__(256) k_agg128() {
    int w = (blockIdx.x * blockDim.x + threadIdx.x) >> 5;
    if (w >= NN) return;
    int lane = threadIdx.x & 31;
    const float4* hp = (const float4*)g_hs;
    float dv = g_dinv[w];
    float4 s = __ldg(hp + w * 32 + lane);
    float ax = s.x, ay = s.y, az = s.z, aw = s.w;
    int beg = g_rowptr[w], end = g_rowptr[w + 1];
    for (int b = beg; b < end; b += 8) {
        int n = end - b;
        int u[8];
        float4 x[8];
#pragma unroll
        for (int j = 0; j < 8; j++) u[j] = (j < n) ? g_colsrc[b + j] : 0;
#pragma unroll
        for (int j = 0; j < 8; j++) {
            if (j < n) x[j] = __ldg(hp + u[j] * 32 + lane);
            else       x[j] = make_float4(0.f, 0.f, 0.f, 0.f);
        }
        ax += ((x[0].x + x[1].x) + (x[2].x + x[3].x)) + ((x[4].x + x[5].x) + (x[6].x + x[7].x));
        ay += ((x[0].y + x[1].y) + (x[2].y + x[3].y)) + ((x[4].y + x[5].y) + (x[6].y + x[7].y));
        az += ((x[0].z + x[1].z) + (x[2].z + x[3].z)) + ((x[4].z + x[5].z) + (x[6].z + x[7].z));
        aw += ((x[0].w + x[1].w) + (x[2].w + x[3].w)) + ((x[4].w + x[5].w) + (x[6].w + x[7].w));
    }
    float4 r = make_float4(ax * dv, ay * dv, az * dv, aw * dv);
    *((float4*)g_agg + w * 32 + lane) = r;
}

// ---------------- GEMMs -------------------------------------------------------

// layer-0 GEMM: [N,16] @ [16,128] + b -> hs = relu(out)*dinv
__global__ void k_gemm0(const float* __restrict__ W0, const float* __restrict__ b0) {
    __shared__ float Ws[16 * 128];
    int t = threadIdx.x;
    for (int i = t; i < 16 * 128; i += 256) Ws[i] = W0[i];
    __syncthreads();
    int row = blockIdx.x * 2 + (t >> 7);
    int col = t & 127;
    float acc = b0[col];
#pragma unroll
    for (int k = 0; k < 16; k++)
        acc += g_agg[row * 16 + k] * Ws[k * 128 + col];
    g_hs[row * HID + col] = fmaxf(acc, 0.f) * g_dinv[row];
}

// tensor-core [N,128]@[128,128] GEMM, bf16 hi/lo split, register-prefetch pipeline.
// emode: 0 = raw out, 1 = relu, 2 = relu * dinv[row]
#define ALD 40
#define WLD 136
__global__ void __launch_bounds__(256, 2)
k_gemm_tc(const float* __restrict__ in, int widx, const float* __restrict__ bias,
          float* __restrict__ out, int relu_in, int emode) {
    __shared__ __nv_bfloat16 a_hi[128 * ALD];
    __shared__ __nv_bfloat16 a_lo[128 * ALD];
    __shared__ __nv_bfloat16 w_hi[32 * WLD];
    __shared__ __nv_bfloat16 w_lo[32 * WLD];
    __shared__ float scratch[8 * 256];

    int t = threadIdx.x;
    int warp = t >> 5;
    int lane = t & 31;
    int warp_r = warp & 3;
    int warp_c = warp >> 2;
    int row0 = blockIdx.x * 128;
    bool full = (row0 + 128 <= NN);

    const __nv_bfloat16* Whi = g_whi + widx * 128 * 128;
    const __nv_bfloat16* Wlo = g_wlo + widx * 128 * 128;

    float4 va[4];
    uint4  vwh[2], vwl[2];

    auto load_chunk = [&](int kc) {
#pragma unroll
        for (int l = 0; l < 4; l++) {
            int idx = t + l * 256;
            int r = idx >> 3, q = idx & 7;
            int gr = row0 + r;
            float4 v = make_float4(0.f, 0.f, 0.f, 0.f);
            if (gr < NN) v = __ldg((const float4*)(in + gr * HID + kc + q * 4));
            va[l] = v;
        }
#pragma unroll
        for (int l = 0; l < 2; l++) {
            int idx = t + l * 256;
            int kr = idx >> 4, q = idx & 15;
            vwh[l] = __ldg((const uint4*)(Whi + (kc + kr) * 128 + q * 8));
            vwl[l] = __ldg((const uint4*)(Wlo + (kc + kr) * 128 + q * 8));
        }
    };
    auto store_chunk = [&]() {
#pragma unroll
        for (int l = 0; l < 4; l++) {
            int idx = t + l * 256;
            int r = idx >> 3, q = idx & 7;
            float vv[4] = {va[l].x, va[l].y, va[l].z, va[l].w};
#pragma unroll
            for (int q2 = 0; q2 < 4; q2++) {
                float f = relu_in ? fmaxf(vv[q2], 0.f) : vv[q2];
                __nv_bfloat16 hi = __float2bfloat16(f);
                a_hi[r * ALD + q * 4 + q2] = hi;
                a_lo[r * ALD + q * 4 + q2] =
                    __float2bfloat16(f - __bfloat162float(hi));
            }
        }
#pragma unroll
        for (int l = 0; l < 2; l++) {
            int idx = t + l * 256;
            int kr = idx >> 4, q = idx & 15;
            *(uint4*)(&w_hi[kr * WLD + q * 8]) = vwh[l];
            *(uint4*)(&w_lo[kr * WLD + q * 8]) = vwl[l];
        }
    };

    wmma::fragment<wmma::accumulator, 16, 16, 16, float> acc[2][4];
#pragma unroll
    for (int i = 0; i < 2; i++)
#pragma unroll
        for (int j = 0; j < 4; j++) wmma::fill_fragment(acc[i][j], 0.0f);

    load_chunk(0);
    store_chunk();
    __syncthreads();

    for (int chunk = 0; chunk < 4; chunk++) {
        if (chunk < 3) load_chunk((chunk + 1) * 32);  // LDG in flight during MMA
#pragma unroll
        for (int ks = 0; ks < 2; ks++) {
            wmma::fragment<wmma::matrix_a, 16, 16, 16, __nv_bfloat16, wmma::row_major> ah[2], al[2];
            wmma::fragment<wmma::matrix_b, 16, 16, 16, __nv_bfloat16, wmma::row_major> bh[4], bl[4];
#pragma unroll
            for (int i = 0; i < 2; i++) {
                wmma::load_matrix_sync(ah[i], &a_hi[(warp_r * 32 + i * 16) * ALD + ks * 16], ALD);
                wmma::load_matrix_sync(al[i], &a_lo[(warp_r * 32 + i * 16) * ALD + ks * 16], ALD);
            }
#pragma unroll
            for (int j = 0; j < 4; j++) {
                wmma::load_matrix_sync(bh[j], &w_hi[(ks * 16) * WLD + warp_c * 64 + j * 16], WLD);
                wmma::load_matrix_sync(bl[j], &w_lo[(ks * 16) * WLD + warp_c * 64 + j * 16], WLD);
            }
#pragma unroll
            for (int i = 0; i < 2; i++)
#pragma unroll
                for (int j = 0; j < 4; j++) {
                    wmma::mma_sync(acc[i][j], ah[i], bh[j], acc[i][j]);
                    wmma::mma_sync(acc[i][j], ah[i], bl[j], acc[i][j]);
                    wmma::mma_sync(acc[i][j], al[i], bh[j], acc[i][j]);
                }
        }
        __syncthreads();
        if (chunk < 3) {
            store_chunk();
            __syncthreads();
        }
    }

    // epilogue
    float* sc = &scratch[warp * 256];
#pragma unroll
    for (int i = 0; i < 2; i++)
#pragma unroll
        for (int j = 0; j < 4; j++) {
            wmma::store_matrix_sync(sc, acc[i][j], 16, wmma::mem_row_major);
            __syncwarp();
#pragma unroll
            for (int e = 0; e < 8; e++) {
                int idx = lane + e * 32;
                int r = idx >> 4, c = idx & 15;
                int gr = row0 + warp_r * 32 + i * 16 + r;
                int gc = warp_c * 64 + j * 16 + c;
                if (full || gr < NN) {
                    float v = sc[idx] + __ldg(&bias[gc]);
                    if (emode >= 1) v = fmaxf(v, 0.f);
                    if (emode == 2) v *= __ldg(&g_dinv[gr]);
                    out[gr * HID + gc] = v;
                }
            }
            __syncwarp();
        }
}

// final head: [N,128] @ [128,3] + b. One warp per row.
__global__ void k_gemm3(const float* __restrict__ in, const float* __restrict__ Wr2,
                        const float* __restrict__ br2, float* __restrict__ out) {
    __shared__ float Ws[128 * 3];
    int t = threadIdx.x;
    for (int i = t; i < 384; i += 256) Ws[i] = Wr2[i];
    __syncthreads();
    int v = (blockIdx.x * blockDim.x + t) >> 5;
    if (v >= NN) return;
    int lane = t & 31;
    float a0 = 0.f, a1 = 0.f, a2 = 0.f;
    for (int k = lane; k < 128; k += 32) {
        float h = in[v * HID + k];
        a0 += h * Ws[k * 3 + 0];
        a1 += h * Ws[k * 3 + 1];
        a2 += h * Ws[k * 3 + 2];
    }
#pragma unroll
    for (int off = 16; off > 0; off >>= 1) {
        a0 += __shfl_xor_sync(0xFFFFFFFF, a0, off);
        a1 += __shfl_xor_sync(0xFFFFFFFF, a1, off);
        a2 += __shfl_xor_sync(0xFFFFFFFF, a2, off);
    }
    if (lane == 0) {
        out[v * 3 + 0] = a0 + br2[0];
        out[v * 3 + 1] = a1 + br2[1];
        out[v * 3 + 2] = a2 + br2[2];
    }
}

// ---------------- launch ------------------------------------------------------

extern "C" void kernel_launch(void* const* d_in, const int* in_sizes, int n_in,
                              void* d_out, int out_size) {
    const float* x    = (const float*)d_in[0];
    const float* xm   = (const float*)d_in[1];
    const int*   ei   = (const int*)d_in[2];
    const float* W0   = (const float*)d_in[3];
    const float* b0   = (const float*)d_in[4];
    const float* Wh   = (const float*)d_in[5];
    const float* bh   = (const float*)d_in[6];
    const float* Wr1  = (const float*)d_in[7];
    const float* br1  = (const float*)d_in[8];
    const float* Wr2  = (const float*)d_in[9];
    const float* br2  = (const float*)d_in[10];
    float* out = (float*)d_out;
    float* out_emb  = out;             // [N,128]
    float* out_pred = out + NN * HID;  // [N,3]

    float* p_agg; cudaGetSymbolAddress((void**)&p_agg, g_agg);
    float* p_hs;  cudaGetSymbolAddress((void**)&p_hs,  g_hs);
    float* p_emb; cudaGetSymbolAddress((void**)&p_emb, g_emb);

    // graph preprocessing + weight split
    k_init<<<(NN + 255) / 256, 256>>>(x, xm);
    k_count<<<(EE + 255) / 256, 256>>>(ei);
    k_wsplit<<<(5 * 128 * 128 + 255) / 256, 256>>>(Wh, Wr1);
    k_scan1<<<NB_SCAN, 1024>>>();
    k_scan2<<<1, 128>>>();
    k_scan3<<<(NN + 255) / 256, 256>>>();
    k_fill<<<(EE + 255) / 256, 256>>>(ei);

    int gemm_blocks = (NN + 127) / 128;

    // layer 0: aggregate 16-dim, then GEMM to 128 (writes hs = relu*dinv)
    k_agg16<<<(NN * 16 + 255) / 256, 256>>>();
    k_gemm0<<<NN / 2, 256>>>(W0, b0);

    // hidden layers 0..3
    for (int i = 0; i < 4; i++) {
        k_agg128<<<(NN * 32 + 255) / 256, 256>>>();
        float* dst   = (i == 3) ? out_emb : p_hs;
        int    emode = (i == 3) ? 0 : 2;
        k_gemm_tc<<<gemm_blocks, 256>>>(p_agg, i, bh + i * 128, dst, 0, emode);
    }

    // head: t = relu(relu(emb) @ Wr1 + br1); pred = t @ Wr2 + br2
    k_gemm_tc<<<gemm_blocks, 256>>>(out_emb, 4, br1, p_emb, 1, 1);
    k_gemm3<<<(NN * 32 + 255) / 256, 256>>>(p_emb, Wr2, br2, out_pred);
}